// round 8
// baseline (speedup 1.0000x reference)
#include <cuda_runtime.h>

#define BB 16
#define NN 64
#define AA 8400
#define CC 20
#define KK 13
#define BA (BB*AA)
#define BN (BB*NN)
#define GB 32                 // bins per axis (20 px bins over 640 px)
#define NBIN (GB*GB)
#define BININV 0.05f          // 1/20
#define LCAP 512              // positive-candidate capacity per row

// ---------------- device scratch (no allocations allowed) ------------------
__device__ int   g_bincnt[NBIN];
__device__ int   g_binstart[NBIN + 1];
__device__ int   g_binpos[NBIN];
__device__ int   g_bidx[AA];             // anchor ids grouped by bin
__device__ float2 g_banc[AA];            // anchor coords grouped by bin
__device__ unsigned long long g_bits[BA];   // pre-filter mask_pos bitmask over n
__device__ unsigned long long g_amax[BA];   // packed (ov_bits<<32 | 63-n) argmax key
__device__ int   g_cand[BN*KK];
__device__ float g_cov[BN*KK];
__device__ float g_cal[BN*KK];
__device__ int   g_cnt[BN];
__device__ float g_norm[BA];
__device__ int   g_lshift;               // 0: labels int32, 1: labels int64

__device__ __forceinline__ int binclamp(int v) { return v < 0 ? 0 : (v > GB-1 ? GB-1 : v); }
__device__ __forceinline__ int lblclamp(int v) { return v < 0 ? 0 : (v > CC-1 ? CC-1 : v); }
// label fetch robust to int32 / int64 storage (detected at runtime)
__device__ __forceinline__ int getlbl(const int* gl, int i, int shift) {
    return lblclamp(__ldg(&gl[i << shift]));
}

// filtered mask_pos bits: pure function of (bits, amax) — no write-back pass
__device__ __forceinline__ unsigned long long filt_bits(unsigned long long bits,
                                                        unsigned long long amax) {
    if (__popcll(bits) > 1) {
        int bi = 63 - (int)(unsigned)(amax & 0xFFFFFFFFull);
        bits &= (1ULL << bi);
    }
    return bits;
}

// ---------------- K_detect: label dtype detection + zero bins (1 block) ----
// int64 labels (values < 2^31) have all odd 32-bit words == 0.
// For int32 labels those words are random in [0,20): P(all zero) ~ 0.
__global__ __launch_bounds__(NBIN) void k_detect(const int* __restrict__ gl) {
    __shared__ int s_ok;
    if (threadIdx.x == 0) s_ok = 1;
    g_bincnt[threadIdx.x] = 0;            // zeroed before k_init_count (stream order)
    __syncthreads();
    if (threadIdx.x < BN) {
        // candidate int64 buffer has 2*BN int32 words; odd words at 2*i+1
        if (__ldg(&gl[2 * threadIdx.x + 1]) != 0) s_ok = 0;
    }
    __syncthreads();
    if (threadIdx.x == 0) g_lshift = s_ok;   // recomputed every call
}

// ---------------- K_init_count: init bits/amax + bin histogram -------------
__global__ void k_init_count(const float* __restrict__ anc) {
    int i = blockIdx.x * blockDim.x + threadIdx.x;
    if (i < BA) { g_bits[i] = 0ULL; g_amax[i] = 63ULL; }  // (ov=0, n=0)
    if (i < AA) {
        float2 ap = __ldg(&((const float2*)anc)[i]);
        int bx = binclamp((int)floorf(ap.x * BININV));
        int by = binclamp((int)floorf(ap.y * BININV));
        atomicAdd(&g_bincnt[by*GB + bx], 1);
    }
}

// ---------------- K_scanscatter: scan bins + scatter anchors (1 block) -----
__global__ __launch_bounds__(NBIN) void k_scanscatter(const float* __restrict__ anc) {
    __shared__ int sc[NBIN];
    int tid = threadIdx.x;
    int c = g_bincnt[tid];
    sc[tid] = c;
    __syncthreads();
    for (int off = 1; off < NBIN; off <<= 1) {
        int v = (tid >= off) ? sc[tid - off] : 0;
        __syncthreads();
        sc[tid] += v;
        __syncthreads();
    }
    int excl = sc[tid] - c;
    g_binstart[tid] = excl;
    g_binpos[tid]   = excl;
    if (tid == NBIN-1) g_binstart[NBIN] = sc[tid];
    __syncthreads();
    for (int i = tid; i < AA; i += NBIN) {
        float2 ap = __ldg(&((const float2*)anc)[i]);
        int bx = binclamp((int)floorf(ap.x * BININV));
        int by = binclamp((int)floorf(ap.y * BININV));
        int p = atomicAdd(&g_binpos[by*GB + bx], 1);
        g_bidx[p] = i;
        g_banc[p] = ap;
    }
}

// ---------------- K_gather: sparse CIoU + exact top-13 per row -------------
__global__ __launch_bounds__(128) void k_gather(
    const float* __restrict__ anc, const float* __restrict__ pdb,
    const int* __restrict__ gl, const float* __restrict__ gtb,
    const float* __restrict__ mgt, const float* __restrict__ ps)
{
    const int row = blockIdx.x;
    const int b = row >> 6, n = row & 63;
    const int tid = threadIdx.x;

    if (__ldg(&mgt[row]) <= 0.0f) { if (tid == 0) g_cnt[row] = 0; return; }

    __shared__ unsigned long long s_key[LCAP];
    __shared__ float s_ovl[LCAP];
    __shared__ unsigned long long s_sel[KK];
    __shared__ float s_selov[KK];
    __shared__ unsigned long long s_red[4];
    __shared__ int s_nv;

    float4 g = __ldg(&((const float4*)gtb)[row]);
    const float gx1 = g.x, gy1 = g.y, gx2 = g.z, gy2 = g.w;
    const float w1 = gx2 - gx1, h1 = gy2 - gy1;
    const float area1 = w1 * h1;
    const float atan1 = atanf(w1 / (h1 + 1e-7f));
    const int lbl0 = getlbl(gl, row, g_lshift);
    const float inv_pi2_4 = 4.0f / (3.14159265358979323846f * 3.14159265358979323846f);

    if (tid == 0) s_nv = 0;
    __syncthreads();

    const int bx0 = binclamp((int)floorf(gx1 * BININV));
    const int bx1 = binclamp((int)floorf(gx2 * BININV));
    const int by0 = binclamp((int)floorf(gy1 * BININV));
    const int by1 = binclamp((int)floorf(gy2 * BININV));

    const float4* __restrict__ pdb4 = &((const float4*)pdb)[(long long)b * AA];

    for (int by = by0; by <= by1; ++by) {
        const int s = g_binstart[by*GB + bx0];
        const int e = g_binstart[by*GB + bx1 + 1];
        for (int j = s + tid; j < e; j += 128) {
            float2 ap = g_banc[j];
            float d = fminf(fminf(ap.x - gx1, ap.y - gy1), fminf(gx2 - ap.x, gy2 - ap.y));
            if (d > 1e-9f) {
                int a = g_bidx[j];
                float4 p = __ldg(&pdb4[a]);
                float iw = fmaxf(fminf(gx2, p.z) - fmaxf(gx1, p.x), 0.0f);
                float ih = fmaxf(fminf(gy2, p.w) - fmaxf(gy1, p.y), 0.0f);
                float inter = iw * ih;
                float w2 = p.z - p.x, h2 = p.w - p.y;
                float uni = area1 + w2 * h2 - inter + 1e-7f;
                float iou = inter / uni;
                float cw = fmaxf(gx2, p.z) - fminf(gx1, p.x);
                float ch = fmaxf(gy2, p.w) - fminf(gy1, p.y);
                float c2 = cw * cw + ch * ch + 1e-7f;
                float dx = (p.x + p.z - gx1 - gx2);
                float dy = (p.y + p.w - gy1 - gy2);
                float rho2 = (dx * dx + dy * dy) * 0.25f;
                float dv = atanf(w2 / (h2 + 1e-7f)) - atan1;
                float v = inv_pi2_4 * dv * dv;
                float alpha = v / (v - iou + (1.0f + 1e-7f));
                float ov = fmaxf(iou - (rho2 / c2 + v * alpha), 0.0f);

                if (ov > 0.0f) {
                    unsigned long long ak =
                        ((unsigned long long)__float_as_uint(ov) << 32) |
                        (unsigned long long)(unsigned)(63 - n);
                    atomicMax(&g_amax[b*AA + a], ak);
                    // align > 0 iff ov > 0 (scores are strictly positive)
                    float sc = __ldg(&ps[((long long)(b*AA + a)) * CC + lbl0]);
                    float ov2 = ov * ov;
                    float align = sc * ov2 * ov2 * ov2;
                    if (align > 0.0f) {
                        int p2 = atomicAdd(&s_nv, 1);
                        if (p2 < LCAP) {
                            s_key[p2] = ((unsigned long long)__float_as_uint(align) << 32) |
                                        (unsigned long long)(0xFFFFFFFFu - (unsigned)a);
                            s_ovl[p2] = ov;
                        }
                    }
                }
            }
        }
    }
    __syncthreads();

    const int nv = min(s_nv, LCAP);
    const int base = row * KK;
    const int lane = tid & 31, wrp = tid >> 5;

    if (nv > KK) {
        // iterative top-13 selection
        for (int r = 0; r < KK; r++) {
            unsigned long long m = 0ULL;
            for (int j = tid; j < nv; j += 128) {
                unsigned long long v2 = s_key[j];
                m = v2 > m ? v2 : m;
            }
#pragma unroll
            for (int off = 16; off > 0; off >>= 1) {
                unsigned long long o = __shfl_down_sync(0xffffffffu, m, off);
                m = o > m ? o : m;
            }
            if (lane == 0) s_red[wrp] = m;
            __syncthreads();
            if (tid == 0) {
                unsigned long long mm = s_red[0];
#pragma unroll
                for (int w = 1; w < 4; w++) mm = s_red[w] > mm ? s_red[w] : mm;
                s_sel[r] = mm;
            }
            __syncthreads();
            unsigned long long best = s_sel[r];
            for (int j = tid; j < nv; j += 128)
                if (s_key[j] == best) { s_selov[r] = s_ovl[j]; s_key[j] = 0ULL; }
            __syncthreads();
        }
        if (tid < KK) {
            unsigned long long key = s_sel[tid];
            int a = (int)(0xFFFFFFFFu - (unsigned)(key & 0xFFFFFFFFull));
            atomicOr(&g_bits[b*AA + a], 1ULL << n);
            g_cand[base + tid] = a;
            g_cov[base + tid] = s_selov[tid];
            g_cal[base + tid] = __uint_as_float((unsigned)(key >> 32));
        }
        if (tid == 0) g_cnt[row] = KK;
    } else {
        // all positives selected
        if (tid < nv) {
            unsigned long long key = s_key[tid];
            int a = (int)(0xFFFFFFFFu - (unsigned)(key & 0xFFFFFFFFull));
            atomicOr(&g_bits[b*AA + a], 1ULL << n);
            g_cand[base + tid] = a;
            g_cov[base + tid] = s_ovl[tid];
            g_cal[base + tid] = __uint_as_float((unsigned)(key >> 32));
        }
        __syncthreads();
        if (tid == 0) {
            // jax top_k zero-fill: remaining picks are the smallest-index
            // anchors with align == 0 (i.e. not in the positive list);
            // need-- for EVERY pick, bits only for picks inside the box
            int cnt = nv;
            int need = KK - nv;
            int a = 0;
            while (need > 0 && a < AA) {
                bool pos = false;
                for (int k2 = 0; k2 < nv; k2++) {
                    int ai = (int)(0xFFFFFFFFu - (unsigned)(s_key[k2] & 0xFFFFFFFFull));
                    if (ai == a) { pos = true; break; }
                }
                if (!pos) {
                    need--;
                    float2 ap = __ldg(&((const float2*)anc)[a]);
                    float d = fminf(fminf(ap.x - gx1, ap.y - gy1),
                                    fminf(gx2 - ap.x, gy2 - ap.y));
                    if (d > 1e-9f) {   // valid zero-align pick enters mask_pos
                        atomicOr(&g_bits[b*AA + a], 1ULL << n);
                        g_cand[base + cnt] = a;
                        g_cov[base + cnt] = 0.0f;
                        g_cal[base + cnt] = 0.0f;
                        cnt++;
                    }
                }
                a++;
            }
            g_cnt[row] = cnt;
        }
    }
}

// ---------------- K_rowstats: pos_align/pos_ov + norm scatter --------------
__global__ void k_rowstats() {
    int row = blockIdx.x * blockDim.x + threadIdx.x;
    if (row >= BN) return;
    int cnt = g_cnt[row];
    if (cnt == 0) return;
    int b = row >> 6, n = row & 63;
    int base = row * KK;
    float pa = 0.0f, po = 0.0f;
    for (int j = 0; j < cnt; j++) {
        int a = g_cand[base + j];
        unsigned long long fb = filt_bits(g_bits[b*AA + a], g_amax[b*AA + a]);
        if ((fb >> n) & 1ULL) {
            pa = fmaxf(pa, g_cal[base + j]);
            po = fmaxf(po, g_cov[base + j]);
        }
    }
    float inv = po / (pa + 1e-9f);
    for (int j = 0; j < cnt; j++) {
        int a = g_cand[base + j];
        unsigned long long fb = filt_bits(g_bits[b*AA + a], g_amax[b*AA + a]);
        if ((fb >> n) & 1ULL)
            g_norm[b*AA + a] = g_cal[base + j] * inv;
    }
}

// ---------------- K_out: all outputs ---------------------------------------
__global__ void k_out(const int* __restrict__ gl,
                      const float* __restrict__ gtb,
                      float* __restrict__ out)
{
    int i = blockIdx.x * blockDim.x + threadIdx.x;
    if (i >= BA) return;
    int b = i / AA;

    unsigned long long bits = filt_bits(g_bits[i], g_amax[i]);
    int fg  = bits ? 1 : 0;
    int tgt = fg ? (__ffsll((long long)bits) - 1) : 0;
    int lbl = getlbl(gl, b*NN + tgt, g_lshift);
    float4 gbx = __ldg(&((const float4*)gtb)[b*NN + tgt]);
    float norm = fg ? g_norm[i] : 0.0f;

    out[i] = (float)lbl;
    ((float4*)(out + BA))[i] = gbx;

    float buf[CC];
#pragma unroll
    for (int c = 0; c < CC; c++) buf[c] = 0.0f;
    if (fg) buf[lbl] = norm;
    float4* o = (float4*)(out + 5*BA + (long long)i * CC);
#pragma unroll
    for (int q = 0; q < CC/4; q++)
        o[q] = make_float4(buf[4*q], buf[4*q+1], buf[4*q+2], buf[4*q+3]);

    out[(5 + CC)*BA + i] = (float)fg;
    out[(6 + CC)*BA + i] = (float)tgt;
}

// ---------------- launcher ---------------------------------------------------
extern "C" void kernel_launch(void* const* d_in, const int* in_sizes, int n_in,
                              void* d_out, int out_size)
{
    const float* pd_scores = (const float*)d_in[0];
    const float* pd_bboxes = (const float*)d_in[1];
    const float* anc       = (const float*)d_in[2];
    const int*   gt_labels = (const int*)d_in[3];   // int32 OR int64 — detected
    const float* gt_bboxes = (const float*)d_in[4];
    const float* mask_gt   = (const float*)d_in[5];
    float* out = (float*)d_out;

    k_detect<<<1, NBIN>>>(gt_labels);
    k_init_count<<<(BA + 255)/256, 256>>>(anc);
    k_scanscatter<<<1, NBIN>>>(anc);
    k_gather<<<BN, 128>>>(anc, pd_bboxes, gt_labels, gt_bboxes, mask_gt, pd_scores);
    k_rowstats<<<(BN + 255)/256, 256>>>();
    k_out<<<(BA + 255)/256, 256>>>(gt_labels, gt_bboxes, out);
}